// round 1
// baseline (speedup 1.0000x reference)
#include <cuda_runtime.h>
#include <cstdint>

// Problem shape (fixed by reference setup_inputs)
#define BB 8
#define NN 32768
#define DD 128
#define HH 64
#define CC 64
#define TOK (BB*NN)

// Scratch (static __device__ globals; no runtime allocation)
__device__ float g_ebuf[TOK];       // exp(sigmoid(mlp)) per token
__device__ float g_denom[BB*CC];    // per-segment softmax denominator

// ---------------------------------------------------------------------------
// K0: zero output + denominator (graph replays re-run this -> deterministic)
// ---------------------------------------------------------------------------
__global__ void init_kernel(float* __restrict__ out) {
    int i = blockIdx.x * blockDim.x + threadIdx.x;
    if (i < BB*CC*DD) out[i] = 0.0f;
    if (i < BB*CC) g_denom[i] = 0.0f;
}

__device__ __forceinline__ uint32_t f2tf32(float v) {
    uint32_t u;
    asm("cvt.rna.tf32.f32 %0, %1;" : "=r"(u) : "f"(v));
    return u;
}

// ---------------------------------------------------------------------------
// K1: fused MLP (tf32 mma.sync) -> e = exp(sigmoid(.)) -> segment denom
// Orientation: D[m=hidden][n=token] = A(W1^T)[m][k] x B(f^T)[k][n]
//   A from smem (W1^T, stride 132 => conflict-free fragment LDS)
//   B direct from gmem (coalesced 16B-per-row pairs, full sector use)
// CTA = 128 threads (4 warps), warp = 32 tokens (4 n-groups of 8)
// ---------------------------------------------------------------------------
__global__ __launch_bounds__(128) void mlp_kernel(
    const float* __restrict__ feat, const int* __restrict__ assign,
    const float* __restrict__ W1, const float* __restrict__ b1,
    const float* __restrict__ W2, const float* __restrict__ b2)
{
    __shared__ uint32_t swA[HH * 132];   // W1^T as tf32 bits, [h][k], stride 132
    __shared__ float sden[CC];
    __shared__ float sW2[HH];
    __shared__ float sb1[HH];

    const int tid  = threadIdx.x;
    const int warp = tid >> 5, lane = tid & 31;
    const int g = lane >> 2, t = lane & 3;   // groupID / threadID_in_group

    // Stage W1^T into smem (tf32-rounded once)
    for (int i = tid; i < DD * HH; i += 128) {
        int k = i >> 6, h = i & 63;          // W1 is [128 k][64 h] row-major
        swA[h * 132 + k] = f2tf32(W1[i]);
    }
    if (tid < HH) { sW2[tid] = W2[tid]; sb1[tid] = b1[tid]; }
    if (tid < CC) sden[tid] = 0.0f;
    __syncthreads();

    // Per-lane epilogue constants: this lane's 8 hidden rows = 16*mt + 8*j + g
    float w2r[8], b1r[8];
    #pragma unroll
    for (int mt = 0; mt < 4; mt++)
        #pragma unroll
        for (int j = 0; j < 2; j++) {
            int r = 16 * mt + 8 * j + g;
            w2r[mt * 2 + j] = sW2[r];
            b1r[mt * 2 + j] = sb1[r];
        }

    const int tokBase = blockIdx.x * 128 + warp * 32;
    const float* fb = feat + (size_t)tokBase * DD;

    float acc[4][4][4];   // [mtile(hidden)][tg(token group)][c0..c3]
    #pragma unroll
    for (int a = 0; a < 4; a++)
        #pragma unroll
        for (int bq = 0; bq < 4; bq++)
            #pragma unroll
            for (int cq = 0; cq < 4; cq++) acc[a][bq][cq] = 0.0f;

    #pragma unroll 4
    for (int k0 = 0; k0 < DD; k0 += 8) {
        // A fragments: a0:(g,t) a1:(g+8,t) a2:(g,t+4) a3:(g+8,t+4)
        uint32_t af[4][4];
        #pragma unroll
        for (int mt = 0; mt < 4; mt++) {
            int base = (16 * mt + g) * 132 + k0 + t;
            af[mt][0] = swA[base];
            af[mt][1] = swA[base + 8 * 132];
            af[mt][2] = swA[base + 4];
            af[mt][3] = swA[base + 8 * 132 + 4];
        }
        // B fragments: b0 = B[k=t][n=g], b1 = B[k=t+4][n=g]; B[k][n]=feat[n][k]
        uint32_t bf[4][2];
        #pragma unroll
        for (int tg = 0; tg < 4; tg++) {
            const float* p = fb + (tg * 8 + g) * DD + k0;
            bf[tg][0] = f2tf32(__ldg(p + t));
            bf[tg][1] = f2tf32(__ldg(p + t + 4));
        }
        #pragma unroll
        for (int mt = 0; mt < 4; mt++)
            #pragma unroll
            for (int tg = 0; tg < 4; tg++) {
                asm volatile(
                    "mma.sync.aligned.m16n8k8.row.col.f32.tf32.tf32.f32 "
                    "{%0,%1,%2,%3}, {%4,%5,%6,%7}, {%8,%9}, {%0,%1,%2,%3};\n"
                    : "+f"(acc[mt][tg][0]), "+f"(acc[mt][tg][1]),
                      "+f"(acc[mt][tg][2]), "+f"(acc[mt][tg][3])
                    : "r"(af[mt][0]), "r"(af[mt][1]), "r"(af[mt][2]), "r"(af[mt][3]),
                      "r"(bf[tg][0]), "r"(bf[tg][1]));
            }
    }

    const float b2v = __ldg(b2);
    const int batch = blockIdx.x >> 8;   // 256 CTAs per batch (32768/128)

    // Epilogue: per token column, dot(relu(h+b1), W2) across 8 lanes (stride 4)
    // c0:(row g, col 2t) c1:(row g, col 2t+1) c2:(row g+8, col 2t) c3:(g+8, 2t+1)
    #pragma unroll
    for (int tg = 0; tg < 4; tg++) {
        float s0 = 0.0f, s1 = 0.0f;
        #pragma unroll
        for (int mt = 0; mt < 4; mt++) {
            s0 += fmaxf(acc[mt][tg][0] + b1r[mt * 2 + 0], 0.0f) * w2r[mt * 2 + 0];
            s1 += fmaxf(acc[mt][tg][1] + b1r[mt * 2 + 0], 0.0f) * w2r[mt * 2 + 0];
            s0 += fmaxf(acc[mt][tg][2] + b1r[mt * 2 + 1], 0.0f) * w2r[mt * 2 + 1];
            s1 += fmaxf(acc[mt][tg][3] + b1r[mt * 2 + 1], 0.0f) * w2r[mt * 2 + 1];
        }
        #pragma unroll
        for (int m = 4; m <= 16; m <<= 1) {
            s0 += __shfl_xor_sync(0xffffffffu, s0, m);
            s1 += __shfl_xor_sync(0xffffffffu, s1, m);
        }
        if (g == 0) {   // lanes 0..3: each owns token cols 2t, 2t+1
            int tok = tokBase + tg * 8 + 2 * t;
            float x0 = s0 + b2v, x1 = s1 + b2v;
            float imp0 = 1.0f / (1.0f + __expf(-x0));
            float imp1 = 1.0f / (1.0f + __expf(-x1));
            float e0 = __expf(imp0), e1 = __expf(imp1);
            *reinterpret_cast<float2*>(&g_ebuf[tok]) = make_float2(e0, e1);
            int2 cl = *reinterpret_cast<const int2*>(&assign[tok]);
            atomicAdd(&sden[cl.x], e0);
            atomicAdd(&sden[cl.y], e1);
        }
    }

    __syncthreads();
    if (tid < CC) atomicAdd(&g_denom[batch * CC + tid], sden[tid]);
}

// ---------------------------------------------------------------------------
// K2: weighted segment sum. 256 threads, 8 warps:
//   warp>>2 = token half (two independent smem accumulator copies -> no races)
//   warp&3  = 32-wide D slice (bank-conflict-free, atomic-free smem RMW)
// Blocks + inner loops run REVERSED so kernel-1's freshest L2 lines hit first.
// ---------------------------------------------------------------------------
__global__ __launch_bounds__(256) void agg_kernel(
    const float* __restrict__ feat, const int* __restrict__ assign,
    float* __restrict__ out)
{
    extern __shared__ float smem[];
    float* acc = smem;                   // 2 * CC * DD floats
    float* sdn = smem + 2 * CC * DD;     // CC floats

    const int tid = threadIdx.x;
    const int warp = tid >> 5, lane = tid & 31;
    const int half = warp >> 2;
    const int ds = (warp & 3) * 32;

    const int gb = (int)gridDim.x - 1 - (int)blockIdx.x;  // reversed mapping
    const int batch = gb >> 5;           // 32 CTAs per batch
    const int chunk = gb & 31;           // 1024 tokens per CTA

    for (int i = tid; i < 2 * CC * DD; i += 256) acc[i] = 0.0f;
    if (tid < CC) sdn[tid] = g_denom[batch * CC + tid];
    __syncthreads();

    float* a = acc + half * CC * DD;
    const int tokStart = batch * NN + chunk * 1024 + half * 512;

    for (int tb = 512 - 32; tb >= 0; tb -= 32) {
        const int t0 = tokStart + tb;
        float e = g_ebuf[t0 + lane];
        int c = assign[t0 + lane];
        float wt = __fdividef(e, sdn[c]);
        #pragma unroll 8
        for (int i = 31; i >= 0; i--) {
            float w  = __shfl_sync(0xffffffffu, wt, i);
            int   cc = __shfl_sync(0xffffffffu, c,  i);
            float f  = __ldg(&feat[(size_t)(t0 + i) * DD + ds + lane]);
            int idx = cc * DD + ds + lane;
            a[idx] += w * f;     // smem RMW; warp-private region -> no atomics
        }
    }
    __syncthreads();

    float* ob = out + batch * CC * DD;
    for (int i = tid; i < CC * DD; i += 256)
        atomicAdd(&ob[i], acc[i] + acc[CC * DD + i]);
}

// ---------------------------------------------------------------------------
extern "C" void kernel_launch(void* const* d_in, const int* in_sizes, int n_in,
                              void* d_out, int out_size) {
    const float* feat   = (const float*)d_in[0];
    const int*   assign = (const int*)d_in[1];
    const float* W1     = (const float*)d_in[2];
    const float* b1     = (const float*)d_in[3];
    const float* W2     = (const float*)d_in[4];
    const float* b2     = (const float*)d_in[5];
    float* out = (float*)d_out;

    const int smem_bytes = (2 * CC * DD + CC) * (int)sizeof(float);  // ~64.25 KB
    cudaFuncSetAttribute(agg_kernel,
                         cudaFuncAttributeMaxDynamicSharedMemorySize, smem_bytes);

    init_kernel<<<(BB * CC * DD + 255) / 256, 256>>>(out);
    mlp_kernel<<<TOK / 128, 128>>>(feat, assign, W1, b1, W2, b2);
    agg_kernel<<<BB * 32, 256, smem_bytes>>>(feat, assign, out);
}

// round 2
// speedup vs baseline: 1.3625x; 1.3625x over previous
#include <cuda_runtime.h>
#include <cstdint>

// Problem shape (fixed by reference setup_inputs)
#define BB 8
#define NN 32768
#define DD 128
#define HH 64
#define CC 64
#define TOK (BB*NN)
#define NSEG (BB*CC)

// Static scratch (no runtime allocation)
__device__ float  g_ebuf[TOK];     // exp(sigmoid(mlp(x))) per token
__device__ float  g_denom[NSEG];   // per-(batch,cluster) softmax denominator
__device__ int    g_count[NSEG];   // per-(batch,cluster) token count
__device__ int    g_off[NSEG];     // exclusive prefix of counts
__device__ int    g_cur[NSEG];     // scatter cursors
__device__ float2 g_pack[TOK];     // segment-sorted (token_id_as_float, weight)

// ---------------------------------------------------------------------------
// K0: zero denominators + counts (1 tiny CTA). Output is fully written by K3.
// ---------------------------------------------------------------------------
__global__ void init_kernel() {
    int i = threadIdx.x;
    g_denom[i] = 0.0f;
    g_count[i] = 0;
}

__device__ __forceinline__ uint32_t f2tf32(float v) {
    uint32_t u;
    asm("cvt.rna.tf32.f32 %0, %1;" : "=r"(u) : "f"(v));
    return u;
}

// ---------------------------------------------------------------------------
// K1: fused MLP (tf32 mma.sync) -> e = exp(sigmoid(.)); segment denom + count.
// D[m=hidden 64][n=token 8/tg] = W1^T x feat^T, k=128.
// B operand: ONE LDG.128 per lane per (tg, 16-k chunk); k is PERMUTED
// consistently in A and B fragments (sum over k is permutation-invariant):
//   logical col t -> physical k0+4t+2s, col t+4 -> k0+4t+2s+1  (s = step 0/1)
// A staged in smem as [k][h] pitch 65 -> LDS bank = (4t+g) mod 32, conflict-free.
// ---------------------------------------------------------------------------
__global__ __launch_bounds__(128) void mlp_kernel(
    const float* __restrict__ feat, const int* __restrict__ assign,
    const float* __restrict__ W1, const float* __restrict__ b1,
    const float* __restrict__ W2, const float* __restrict__ b2)
{
    __shared__ uint32_t swA[DD * 65];   // W1 as tf32 bits, [k][h], pitch 65
    __shared__ float sden[CC];
    __shared__ int   scnt[CC];
    __shared__ float sW2[HH], sb1[HH];

    const int tid  = threadIdx.x;
    const int warp = tid >> 5, lane = tid & 31;
    const int g = lane >> 2, t = lane & 3;

    for (int i = tid; i < DD * HH; i += 128) {
        int k = i >> 6, h = i & 63;        // W1 row-major [128 k][64 h]
        swA[k * 65 + h] = f2tf32(W1[i]);
    }
    if (tid < HH) { sW2[tid] = W2[tid]; sb1[tid] = b1[tid]; }
    if (tid < CC) { sden[tid] = 0.0f; scnt[tid] = 0; }
    __syncthreads();

    // Per-lane epilogue constants: lane's 8 hidden rows = 16*mt + 8*j + g
    float w2r[8], b1r[8];
    #pragma unroll
    for (int mt = 0; mt < 4; mt++)
        #pragma unroll
        for (int jj = 0; jj < 2; jj++) {
            int r = 16 * mt + 8 * jj + g;
            w2r[mt * 2 + jj] = sW2[r];
            b1r[mt * 2 + jj] = sb1[r];
        }

    const int tokBase = blockIdx.x * 128 + warp * 32;
    const float4* fb4 = reinterpret_cast<const float4*>(feat + (size_t)tokBase * DD);

    float acc[4][4][4];   // [mtile(hidden)][tg(token group)][c0..c3]
    #pragma unroll
    for (int a = 0; a < 4; a++)
        #pragma unroll
        for (int bq = 0; bq < 4; bq++)
            #pragma unroll
            for (int cq = 0; cq < 4; cq++) acc[a][bq][cq] = 0.0f;

    #pragma unroll
    for (int kc = 0; kc < 8; kc++) {       // 16-k chunks
        const int k0 = kc * 16;
        float4 fv[4];                       // lane (g,t): feat[tg*8+g][k0+4t..+3]
        #pragma unroll
        for (int tg = 0; tg < 4; tg++)
            fv[tg] = __ldg(&fb4[(tg * 8 + g) * 32 + (k0 >> 2) + t]);

        #pragma unroll
        for (int s = 0; s < 2; s++) {      // two k8 MMA steps per chunk
            const int ka = k0 + 4 * t + 2 * s;   // physical k for logical col t
            uint32_t af[4][4];
            #pragma unroll
            for (int mt = 0; mt < 4; mt++) {
                int r = 16 * mt + g;
                af[mt][0] = swA[ka * 65 + r];            // (row g,   col t)
                af[mt][1] = swA[ka * 65 + r + 8];        // (row g+8, col t)
                af[mt][2] = swA[(ka + 1) * 65 + r];      // (row g,   col t+4)
                af[mt][3] = swA[(ka + 1) * 65 + r + 8];  // (row g+8, col t+4)
            }
            #pragma unroll
            for (int tg = 0; tg < 4; tg++) {
                uint32_t bu0 = f2tf32(s ? fv[tg].z : fv[tg].x);
                uint32_t bu1 = f2tf32(s ? fv[tg].w : fv[tg].y);
                #pragma unroll
                for (int mt = 0; mt < 4; mt++) {
                    asm volatile(
                        "mma.sync.aligned.m16n8k8.row.col.f32.tf32.tf32.f32 "
                        "{%0,%1,%2,%3}, {%4,%5,%6,%7}, {%8,%9}, {%0,%1,%2,%3};\n"
                        : "+f"(acc[mt][tg][0]), "+f"(acc[mt][tg][1]),
                          "+f"(acc[mt][tg][2]), "+f"(acc[mt][tg][3])
                        : "r"(af[mt][0]), "r"(af[mt][1]), "r"(af[mt][2]), "r"(af[mt][3]),
                          "r"(bu0), "r"(bu1));
                }
            }
        }
    }

    const float b2v = __ldg(b2);
    const int batch = blockIdx.x >> 8;     // 256 CTAs per batch

    // Epilogue: D col n held by lane t as cols {2t, 2t+1}; rows reduced over g.
    #pragma unroll
    for (int tg = 0; tg < 4; tg++) {
        float s0 = 0.0f, s1 = 0.0f;
        #pragma unroll
        for (int mt = 0; mt < 4; mt++) {
            s0 += fmaxf(acc[mt][tg][0] + b1r[mt * 2 + 0], 0.0f) * w2r[mt * 2 + 0];
            s1 += fmaxf(acc[mt][tg][1] + b1r[mt * 2 + 0], 0.0f) * w2r[mt * 2 + 0];
            s0 += fmaxf(acc[mt][tg][2] + b1r[mt * 2 + 1], 0.0f) * w2r[mt * 2 + 1];
            s1 += fmaxf(acc[mt][tg][3] + b1r[mt * 2 + 1], 0.0f) * w2r[mt * 2 + 1];
        }
        #pragma unroll
        for (int m = 4; m <= 16; m <<= 1) {
            s0 += __shfl_xor_sync(0xffffffffu, s0, m);
            s1 += __shfl_xor_sync(0xffffffffu, s1, m);
        }
        if (g == 0) {   // lanes 0..3 own token cols 2t, 2t+1
            int tok = tokBase + tg * 8 + 2 * t;
            float x0 = s0 + b2v, x1 = s1 + b2v;
            float imp0 = 1.0f / (1.0f + __expf(-x0));
            float imp1 = 1.0f / (1.0f + __expf(-x1));
            float e0 = __expf(imp0), e1 = __expf(imp1);
            *reinterpret_cast<float2*>(&g_ebuf[tok]) = make_float2(e0, e1);
            int2 cl = *reinterpret_cast<const int2*>(&assign[tok]);
            atomicAdd(&sden[cl.x], e0);
            atomicAdd(&sden[cl.y], e1);
            atomicAdd(&scnt[cl.x], 1);
            atomicAdd(&scnt[cl.y], 1);
        }
    }

    __syncthreads();
    if (tid < CC) {
        atomicAdd(&g_denom[batch * CC + tid], sden[tid]);
        atomicAdd(&g_count[batch * CC + tid], scnt[tid]);
    }
}

// ---------------------------------------------------------------------------
// K2a: exclusive scan of 512 segment counts -> g_off, g_cur. 1 CTA.
// ---------------------------------------------------------------------------
__global__ void scan_kernel() {
    __shared__ int s[NSEG];
    const int tid = threadIdx.x;
    const int v = g_count[tid];
    s[tid] = v;
    __syncthreads();
    for (int d = 1; d < NSEG; d <<= 1) {
        int x = (tid >= d) ? s[tid - d] : 0;
        __syncthreads();
        s[tid] += x;
        __syncthreads();
    }
    const int off = s[tid] - v;   // exclusive prefix
    g_off[tid] = off;
    g_cur[tid] = off;
}

// ---------------------------------------------------------------------------
// K2b: scatter tokens into segment-sorted order with (token,weight) packed.
// Smem-aggregated cursors: 2 smem atomics/token + 64 global atomics/CTA.
// ---------------------------------------------------------------------------
__global__ __launch_bounds__(256) void scatter_kernel(const int* __restrict__ assign) {
    __shared__ int scur[CC];
    __shared__ int sbase[CC];
    const int tid = threadIdx.x;
    if (tid < CC) scur[tid] = 0;
    __syncthreads();

    const int i = blockIdx.x * 256 + tid;      // 128 CTAs per batch
    const int cl = assign[i];
    const int posl = atomicAdd(&scur[cl], 1);
    __syncthreads();

    const int batch = i >> 15;
    if (tid < CC) {
        int seg = (blockIdx.x >> 7) * CC + tid;
        sbase[tid] = atomicAdd(&g_cur[seg], scur[tid]);
    }
    __syncthreads();

    const float e = g_ebuf[i];
    const float w = __fdividef(e, g_denom[batch * CC + cl]);
    g_pack[sbase[cl] + posl] = make_float2(__int_as_float(i), w);
}

// ---------------------------------------------------------------------------
// K3: gather-sum. One CTA per segment; 4 warps stride the token list; each
// lane accumulates a float4 D-slice in REGISTERS (no RMW chain, no atomics).
// One LDG.128 per lane = whole 512B feature row per warp, fully coalesced.
// ---------------------------------------------------------------------------
__global__ __launch_bounds__(128) void gather_kernel(
    const float* __restrict__ feat, float* __restrict__ out)
{
    __shared__ float red[4 * DD];
    const int tid = threadIdx.x, warp = tid >> 5, lane = tid & 31;
    const int seg = blockIdx.x;
    const int off = g_off[seg];
    const int cnt = g_count[seg];
    const float4* f4 = reinterpret_cast<const float4*>(feat);

    float4 acc = make_float4(0.0f, 0.0f, 0.0f, 0.0f);

    int j = warp;
    for (; j + 12 < cnt; j += 16) {   // 4 tokens per warp per iteration (MLP=4)
        float2 p0 = g_pack[off + j];
        float2 p1 = g_pack[off + j + 4];
        float2 p2 = g_pack[off + j + 8];
        float2 p3 = g_pack[off + j + 12];
        float4 f0 = __ldg(&f4[(size_t)__float_as_int(p0.x) * 32 + lane]);
        float4 f1 = __ldg(&f4[(size_t)__float_as_int(p1.x) * 32 + lane]);
        float4 f2 = __ldg(&f4[(size_t)__float_as_int(p2.x) * 32 + lane]);
        float4 f3 = __ldg(&f4[(size_t)__float_as_int(p3.x) * 32 + lane]);
        acc.x += p0.y * f0.x; acc.y += p0.y * f0.y; acc.z += p0.y * f0.z; acc.w += p0.y * f0.w;
        acc.x += p1.y * f1.x; acc.y += p1.y * f1.y; acc.z += p1.y * f1.z; acc.w += p1.y * f1.w;
        acc.x += p2.y * f2.x; acc.y += p2.y * f2.y; acc.z += p2.y * f2.z; acc.w += p2.y * f2.w;
        acc.x += p3.y * f3.x; acc.y += p3.y * f3.y; acc.z += p3.y * f3.z; acc.w += p3.y * f3.w;
    }
    for (; j < cnt; j += 4) {
        float2 p = g_pack[off + j];
        float4 f = __ldg(&f4[(size_t)__float_as_int(p.x) * 32 + lane]);
        acc.x += p.y * f.x; acc.y += p.y * f.y; acc.z += p.y * f.z; acc.w += p.y * f.w;
    }

    reinterpret_cast<float4*>(red)[warp * 32 + lane] = acc;
    __syncthreads();
    out[seg * DD + tid] = red[tid] + red[DD + tid] + red[2 * DD + tid] + red[3 * DD + tid];
}

// ---------------------------------------------------------------------------
extern "C" void kernel_launch(void* const* d_in, const int* in_sizes, int n_in,
                              void* d_out, int out_size) {
    const float* feat   = (const float*)d_in[0];
    const int*   assign = (const int*)d_in[1];
    const float* W1     = (const float*)d_in[2];
    const float* b1     = (const float*)d_in[3];
    const float* W2     = (const float*)d_in[4];
    const float* b2     = (const float*)d_in[5];
    float* out = (float*)d_out;

    init_kernel<<<1, NSEG>>>();
    mlp_kernel<<<TOK / 128, 128>>>(feat, assign, W1, b1, W2, b2);
    scan_kernel<<<1, NSEG>>>();
    scatter_kernel<<<TOK / 256, 256>>>(assign);
    gather_kernel<<<NSEG, 128>>>(feat, out);
}